// round 16
// baseline (speedup 1.0000x reference)
#include <cuda_runtime.h>
#include <cuda_fp16.h>
#include <cstdint>

// Problem constants (from reference setup_inputs)
#define NMAX 50048
#define EMAX 1600000
#define F 128

// Scratch (allocation-free rule: __device__ globals)
__device__ __align__(16) __half g_p[NMAX * F];    // pool outputs (p1, then p2)
__device__ __align__(16) __half g_agg[NMAX * F];  // segment max
__device__ __align__(16) __half g_h1[NMAX * F];   // layer-1 output
__device__ __align__(16) __half g_x16[NMAX * F];  // fp16 copy of x (written by pool1)
__device__ __align__(16) __half g_w[6 * F * F];   // fp16 weights

// CSR-by-dst scratch (g_cnt[NMAX-1] doubles as the slot-allocator counter)
__device__ int g_cnt[NMAX];
__device__ int g_rowptr[NMAX + 1];
__device__ int g_cursor[NMAX];
__device__ int g_eidx[EMAX];

// ---------------------------------------------------------------------------
// Helpers
// ---------------------------------------------------------------------------
__device__ __forceinline__ void cp16(void* smem_dst, const void* gsrc) {
    unsigned d = (unsigned)__cvta_generic_to_shared(smem_dst);
    asm volatile("cp.async.cg.shared.global [%0], [%1], 16;" :: "r"(d), "l"(gsrc));
}
#define CP_COMMIT() asm volatile("cp.async.commit_group;")
#define CP_WAIT0()  asm volatile("cp.async.wait_group 0;")

__device__ __forceinline__ void mma_f16(float* d, const unsigned* a, const unsigned* b) {
    asm volatile(
        "mma.sync.aligned.m16n8k16.row.col.f32.f16.f16.f32 "
        "{%0,%1,%2,%3}, {%4,%5,%6,%7}, {%8,%9}, {%0,%1,%2,%3};"
        : "+f"(d[0]), "+f"(d[1]), "+f"(d[2]), "+f"(d[3])
        : "r"(a[0]), "r"(a[1]), "r"(a[2]), "r"(a[3]), "r"(b[0]), "r"(b[1]));
}

__device__ __forceinline__ void ldsm_x4(unsigned* a, unsigned saddr) {
    asm volatile("ldmatrix.sync.aligned.m8n8.x4.shared.b16 {%0,%1,%2,%3}, [%4];"
        : "=r"(a[0]), "=r"(a[1]), "=r"(a[2]), "=r"(a[3]) : "r"(saddr));
}
__device__ __forceinline__ void ldsm_x2_trans(unsigned* b, unsigned saddr) {
    asm volatile("ldmatrix.sync.aligned.m8n8.x2.trans.shared.b16 {%0,%1}, [%2];"
        : "=r"(b[0]), "=r"(b[1]) : "r"(saddr));
}
// x4 trans: loads a 16(k) x 16(n) b16 tile = fragments for TWO adjacent n-frags.
// r0,r1 = cols [0,8) (k0-7, k8-15); r2,r3 = cols [8,16).
__device__ __forceinline__ void ldsm_x4_trans(unsigned* b, unsigned saddr) {
    asm volatile("ldmatrix.sync.aligned.m8n8.x4.trans.shared.b16 {%0,%1,%2,%3}, [%4];"
        : "=r"(b[0]), "=r"(b[1]), "=r"(b[2]), "=r"(b[3]) : "r"(saddr));
}

// ---------------------------------------------------------------------------
// Prep: convert 6 weight matrices to fp16 (once per launch)
// ---------------------------------------------------------------------------
__global__ void conv_w_kernel(const float* w0, const float* w1, const float* w2,
                              const float* w3, const float* w4, const float* w5,
                              __half* __restrict__ out)
{
    const float* ws[6] = {w0, w1, w2, w3, w4, w5};
    const float* in = ws[blockIdx.y];
    __half* o = out + blockIdx.y * (F * F);
    int i = blockIdx.x * blockDim.x + threadIdx.x;
    float4 v0 = ((const float4*)in)[i * 2];
    float4 v1 = ((const float4*)in)[i * 2 + 1];
    __half2 h[4];
    h[0] = __floats2half2_rn(v0.x, v0.y);
    h[1] = __floats2half2_rn(v0.z, v0.w);
    h[2] = __floats2half2_rn(v1.x, v1.y);
    h[3] = __floats2half2_rn(v1.z, v1.w);
    ((float4*)o)[i] = *(float4*)h;
}

// ---------------------------------------------------------------------------
// Tiling constants
// ---------------------------------------------------------------------------
#define SAH 72
#define SBH 136
#define AS_ELEM (64 * SAH)
#define BS_ELEM (64 * SBH)
#define AS_BYTES (AS_ELEM * 2)
#define BS_BYTES (BS_ELEM * 2)
#define SMEM_BYTES (2 * AS_BYTES + 2 * BS_BYTES)      // pool1 (2-buffer)
#define H1_STRIDE 136
#define ROWSQ_OFF 17408
// Fused kernel: 4 A buffers + 4 B buffers, full prefetch
#define FB_OFF (4 * AS_BYTES)
#define FUSED_SMEM (4 * AS_BYTES + 4 * BS_BYTES)      // 106496 bytes

__device__ __forceinline__ void prefetch_A(char* smc, const __half* A,
                                           int buf, int kk, int m0, int M, int tid)
{
    __half* As = (__half*)smc;
#pragma unroll
    for (int i = 0; i < 2; i++) {
        int c  = tid + i * 256;
        int r  = c >> 3;
        int c8 = (c & 7) * 8;
        int m  = m0 + r;
        if (m < M)
            cp16(&As[buf * AS_ELEM + r * SAH + c8], A + (size_t)m * F + kk + c8);
    }
}

__device__ __forceinline__ void prefetch_B2(char* smc, const __half* W,
                                            int buf, int kk, int tid)
{
    __half* Bs = (__half*)(smc + 2 * AS_BYTES);   // pool1 layout (2 A bufs)
#pragma unroll
    for (int i = 0; i < 4; i++) {
        int c  = tid + i * 256;
        int r  = c >> 4;
        int n8 = (c & 15) * 8;
        cp16(&Bs[buf * BS_ELEM + r * SBH + n8], W + (size_t)(kk + r) * F + n8);
    }
}

__device__ __forceinline__ void prefetch_B4(char* smc, const __half* W,
                                            int buf, int kk, int tid)
{
    __half* Bs = (__half*)(smc + FB_OFF);         // fused layout (4 A bufs)
#pragma unroll
    for (int i = 0; i < 4; i++) {
        int c  = tid + i * 256;
        int r  = c >> 4;
        int n8 = (c & 15) * 8;
        cp16(&Bs[buf * BS_ELEM + r * SBH + n8], W + (size_t)(kk + r) * F + n8);
    }
}

// ---------------------------------------------------------------------------
// Pool GEMM layer 1, fused x-conversion (unchanged from R14/R15).
// ---------------------------------------------------------------------------
__global__ __launch_bounds__(256, 3)
void pool1_kernel(const float* __restrict__ x, const __half* __restrict__ W1,
                  const float* __restrict__ bias,
                  __half* __restrict__ x16, __half* __restrict__ Pout, int M)
{
    extern __shared__ __align__(16) char smc[];
    __half* As = (__half*)smc;

    const int tid  = threadIdx.x;
    const int wid  = tid >> 5;
    const int lane = tid & 31;
    const int wr   = wid >> 2;
    const int wc   = wid & 3;
    const int g    = lane >> 2;
    const int tig  = lane & 3;
    const int m0   = blockIdx.x * 64;

    prefetch_B2(smc, W1, 0, 0, tid);
    prefetch_B2(smc, W1, 1, 64, tid);
    CP_COMMIT();

#pragma unroll
    for (int t = 0; t < 2; t++) {
        float4 v[4];
        int rr[4], cc[4];
#pragma unroll
        for (int i = 0; i < 4; i++) {
            int idx = tid + i * 256;
            rr[i] = idx >> 4;
            cc[i] = (idx & 15) * 4;
            int m = m0 + rr[i];
            v[i] = make_float4(0.f, 0.f, 0.f, 0.f);
            if (m < M) v[i] = *(const float4*)(x + (size_t)m * F + t * 64 + cc[i]);
        }
#pragma unroll
        for (int i = 0; i < 4; i++) {
            __half2 h0 = __floats2half2_rn(v[i].x, v[i].y);
            __half2 h1 = __floats2half2_rn(v[i].z, v[i].w);
            __half2 pair[2] = {h0, h1};
            *(uint2*)(As + t * AS_ELEM + rr[i] * SAH + cc[i]) = *(uint2*)pair;
            int m = m0 + rr[i];
            if (m < M)
                *(uint2*)(x16 + (size_t)m * F + t * 64 + cc[i]) = *(uint2*)pair;
        }
    }

    unsigned as_u32 = (unsigned)__cvta_generic_to_shared(smc);
    unsigned bs_u32 = (unsigned)__cvta_generic_to_shared(smc + 2 * AS_BYTES);
    const int lrow = lane & 15;
    const int kadd = (lane & 16) ? 8 : 0;
    unsigned aaddr[2];
#pragma unroll
    for (int mf = 0; mf < 2; mf++)
        aaddr[mf] = as_u32 + ((wr * 32 + mf * 16 + lrow) * SAH + kadd) * 2;
    // x4-trans B addresses: one per nf-pair
    unsigned baddr2[2];
#pragma unroll
    for (int j = 0; j < 2; j++)
        baddr2[j] = bs_u32 + (lrow * SBH + wc * 32 + j * 16 + kadd) * 2;

    float acc[2][4][4];
#pragma unroll
    for (int mf = 0; mf < 2; mf++)
#pragma unroll
        for (int nf = 0; nf < 4; nf++)
#pragma unroll
            for (int q = 0; q < 4; q++) acc[mf][nf][q] = 0.0f;

    CP_WAIT0();
    __syncthreads();

#pragma unroll
    for (int t = 0; t < 2; t++) {
#pragma unroll
        for (int s = 0; s < 4; s++) {
            unsigned a[2][4], b[2][4];
#pragma unroll
            for (int mf = 0; mf < 2; mf++)
                ldsm_x4(a[mf], aaddr[mf] + t * AS_BYTES + s * 32);
#pragma unroll
            for (int j = 0; j < 2; j++)
                ldsm_x4_trans(b[j], baddr2[j] + t * BS_BYTES + s * (16 * SBH * 2));
#pragma unroll
            for (int mf = 0; mf < 2; mf++)
#pragma unroll
                for (int nf = 0; nf < 4; nf++)
                    mma_f16(acc[mf][nf], a[mf], &b[nf >> 1][(nf & 1) * 2]);
        }
    }

    float bv0[4], bv1[4];
#pragma unroll
    for (int nf = 0; nf < 4; nf++) {
        int cb = wc * 32 + nf * 8 + 2 * tig;
        bv0[nf] = bias[cb];
        bv1[nf] = bias[cb + 1];
    }
#pragma unroll
    for (int mf = 0; mf < 2; mf++) {
#pragma unroll
        for (int half = 0; half < 2; half++) {
            int m = m0 + wr * 32 + mf * 16 + half * 8 + g;
            if (m >= M) continue;
#pragma unroll
            for (int nf = 0; nf < 4; nf++) {
                float v0 = fmaxf(acc[mf][nf][half * 2 + 0] + bv0[nf], 0.f);
                float v1 = fmaxf(acc[mf][nf][half * 2 + 1] + bv1[nf], 0.f);
                int col = wc * 32 + nf * 8 + 2 * tig;
                __half2 hv = __floats2half2_rn(v0, v1);
                *(__half2*)(Pout + (size_t)m * F + col) = hv;
            }
        }
    }
}

// ---------------------------------------------------------------------------
// Fused GEMM: load-all / wait-once / compute-all.
// C = epi( A1@W1 + A2@W2 + bias ); optional POOL2 tail from smem C tile.
// All 8 tile loads in ONE cp.async group; a single wait+barrier; then a
// 16-iteration barrier-free mainloop (compiler pipelines LDSM ahead of MMA).
// ---------------------------------------------------------------------------
template<bool HALFOUT, bool POOL2>
__global__ __launch_bounds__(256, 2)
void fused_gemm_kernel(const __half* __restrict__ A1, const __half* __restrict__ W1,
                       const __half* __restrict__ A2, const __half* __restrict__ W2,
                       const float* __restrict__ bias, void* __restrict__ Cout,
                       const __half* __restrict__ Wp2, const float* __restrict__ bias2,
                       __half* __restrict__ Pout, int M)
{
    extern __shared__ __align__(16) char smc[];

    const int tid  = threadIdx.x;
    const int wid  = tid >> 5;
    const int lane = tid & 31;
    const int wr   = wid >> 2;
    const int wc   = wid & 3;
    const int g    = lane >> 2;
    const int tig  = lane & 3;
    const int m0   = blockIdx.x * 64;

    // Issue ALL tile loads up front, one group.
    prefetch_A(smc, A1, 0, 0,  m0, M, tid); prefetch_B4(smc, W1, 0, 0,  tid);
    prefetch_A(smc, A1, 1, 64, m0, M, tid); prefetch_B4(smc, W1, 1, 64, tid);
    prefetch_A(smc, A2, 2, 0,  m0, M, tid); prefetch_B4(smc, W2, 2, 0,  tid);
    prefetch_A(smc, A2, 3, 64, m0, M, tid); prefetch_B4(smc, W2, 3, 64, tid);
    CP_COMMIT();

    unsigned as_u32 = (unsigned)__cvta_generic_to_shared(smc);
    unsigned bs_u32 = (unsigned)__cvta_generic_to_shared(smc + FB_OFF);
    const int lrow = lane & 15;
    const int kadd = (lane & 16) ? 8 : 0;
    unsigned aaddr[2];
#pragma unroll
    for (int mf = 0; mf < 2; mf++)
        aaddr[mf] = as_u32 + ((wr * 32 + mf * 16 + lrow) * SAH + kadd) * 2;
    unsigned baddr2[2];
#pragma unroll
    for (int j = 0; j < 2; j++)
        baddr2[j] = bs_u32 + (lrow * SBH + wc * 32 + j * 16 + kadd) * 2;

    float acc[2][4][4];
#pragma unroll
    for (int mf = 0; mf < 2; mf++)
#pragma unroll
        for (int nf = 0; nf < 4; nf++)
#pragma unroll
            for (int q = 0; q < 4; q++) acc[mf][nf][q] = 0.0f;

    CP_WAIT0();
    __syncthreads();

    // Barrier-free mainloop: 4 tiles x 4 k-steps.
#pragma unroll
    for (int t = 0; t < 4; t++) {
#pragma unroll
        for (int s = 0; s < 4; s++) {
            unsigned a[2][4], b[2][4];
#pragma unroll
            for (int mf = 0; mf < 2; mf++)
                ldsm_x4(a[mf], aaddr[mf] + t * AS_BYTES + s * 32);
#pragma unroll
            for (int j = 0; j < 2; j++)
                ldsm_x4_trans(b[j], baddr2[j] + t * BS_BYTES + s * (16 * SBH * 2));
#pragma unroll
            for (int mf = 0; mf < 2; mf++)
#pragma unroll
                for (int nf = 0; nf < 4; nf++)
                    mma_f16(acc[mf][nf], a[mf], &b[nf >> 1][(nf & 1) * 2]);
        }
    }

    // ---- epilogue ----
    __syncthreads();

    if (POOL2) {
        // prefetch full Wp2 into B buffers 0,1 (dead now)
#pragma unroll
        for (int i = 0; i < 8; i++) {
            int c   = tid + i * 256;
            int buf = c >> 10;
            int cc  = c & 1023;
            int r   = cc >> 4;
            int n8  = (cc & 15) * 8;
            cp16((__half*)(smc + FB_OFF) + buf * BS_ELEM + r * SBH + n8,
                 Wp2 + (size_t)(buf * 64 + r) * F + n8);
        }
        CP_COMMIT();
    }

    float bv0[4], bv1[4];
#pragma unroll
    for (int nf = 0; nf < 4; nf++) {
        int cb = wc * 32 + nf * 8 + 2 * tig;
        bv0[nf] = bias[cb];
        bv1[nf] = bias[cb + 1];
    }
#pragma unroll
    for (int mf = 0; mf < 2; mf++)
#pragma unroll
        for (int nf = 0; nf < 4; nf++) {
            acc[mf][nf][0] += bv0[nf];
            acc[mf][nf][1] += bv1[nf];
            acc[mf][nf][2] += bv0[nf];
            acc[mf][nf][3] += bv1[nf];
        }

    // L2 norm (always on for fused layers)
    float inv[2][2];
    {
        float* rowsq = (float*)(smc + ROWSQ_OFF);
        if (tid < 64) rowsq[tid] = 0.0f;
        __syncthreads();
#pragma unroll
        for (int mf = 0; mf < 2; mf++) {
#pragma unroll
            for (int half = 0; half < 2; half++) {
                float s = 0.f;
#pragma unroll
                for (int nf = 0; nf < 4; nf++) {
                    float v0 = acc[mf][nf][half * 2 + 0];
                    float v1 = acc[mf][nf][half * 2 + 1];
                    s = fmaf(v0, v0, fmaf(v1, v1, s));
                }
                s += __shfl_xor_sync(0xffffffffu, s, 1);
                s += __shfl_xor_sync(0xffffffffu, s, 2);
                if (tig == 0) {
                    int r = wr * 32 + mf * 16 + half * 8 + g;
                    atomicAdd(&rowsq[r], s);
                }
            }
        }
        __syncthreads();
#pragma unroll
        for (int mf = 0; mf < 2; mf++)
#pragma unroll
            for (int half = 0; half < 2; half++) {
                int r = wr * 32 + mf * 16 + half * 8 + g;
                inv[mf][half] = 1.0f / fmaxf(sqrtf(rowsq[r]), 1e-12f);
            }
    }

    // store (relu); POOL2 mirrors the C tile into smem (A region, dead)
#pragma unroll
    for (int mf = 0; mf < 2; mf++) {
#pragma unroll
        for (int half = 0; half < 2; half++) {
            int mloc = wr * 32 + mf * 16 + half * 8 + g;
            int m = m0 + mloc;
            float s = inv[mf][half];
#pragma unroll
            for (int nf = 0; nf < 4; nf++) {
                float v0 = fmaxf(acc[mf][nf][half * 2 + 0] * s, 0.f);
                float v1 = fmaxf(acc[mf][nf][half * 2 + 1] * s, 0.f);
                int col = wc * 32 + nf * 8 + 2 * tig;
                if (HALFOUT) {
                    __half2 hv = __floats2half2_rn(v0, v1);
                    if (m < M)
                        *(__half2*)((__half*)Cout + (size_t)m * F + col) = hv;
                    if (POOL2)
                        *(__half2*)(smc + (mloc * H1_STRIDE + col) * 2) = hv;
                } else {
                    if (m < M)
                        *(float2*)((float*)Cout + (size_t)m * F + col) = make_float2(v0, v1);
                }
            }
        }
    }

    if (POOL2) {
        CP_WAIT0();
        __syncthreads();

        unsigned a2addr[2];
#pragma unroll
        for (int mf = 0; mf < 2; mf++)
            a2addr[mf] = as_u32 + ((wr * 32 + mf * 16 + lrow) * H1_STRIDE + kadd) * 2;

        float acc2[2][4][4];
#pragma unroll
        for (int mf = 0; mf < 2; mf++)
#pragma unroll
            for (int nf = 0; nf < 4; nf++)
#pragma unroll
                for (int q = 0; q < 4; q++) acc2[mf][nf][q] = 0.0f;

#pragma unroll
        for (int t = 0; t < 2; t++) {
#pragma unroll
            for (int s = 0; s < 4; s++) {
                unsigned a[2][4], b[2][4];
#pragma unroll
                for (int mf = 0; mf < 2; mf++)
                    ldsm_x4(a[mf], a2addr[mf] + (t * 64 + s * 16) * 2);
#pragma unroll
                for (int j = 0; j < 2; j++)
                    ldsm_x4_trans(b[j], baddr2[j] + t * BS_BYTES + s * (16 * SBH * 2));
#pragma unroll
                for (int mf = 0; mf < 2; mf++)
#pragma unroll
                    for (int nf = 0; nf < 4; nf++)
                        mma_f16(acc2[mf][nf], a[mf], &b[nf >> 1][(nf & 1) * 2]);
            }
        }

        float pb0[4], pb1[4];
#pragma unroll
        for (int nf = 0; nf < 4; nf++) {
            int cb = wc * 32 + nf * 8 + 2 * tig;
            pb0[nf] = bias2[cb];
            pb1[nf] = bias2[cb + 1];
        }
#pragma unroll
        for (int mf = 0; mf < 2; mf++) {
#pragma unroll
            for (int half = 0; half < 2; half++) {
                int m = m0 + wr * 32 + mf * 16 + half * 8 + g;
                if (m >= M) continue;
#pragma unroll
                for (int nf = 0; nf < 4; nf++) {
                    float v0 = fmaxf(acc2[mf][nf][half * 2 + 0] + pb0[nf], 0.f);
                    float v1 = fmaxf(acc2[mf][nf][half * 2 + 1] + pb1[nf], 0.f);
                    int col = wc * 32 + nf * 8 + 2 * tig;
                    __half2 hv = __floats2half2_rn(v0, v1);
                    *(__half2*)(Pout + (size_t)m * F + col) = hv;
                }
            }
        }
    }
}

// ---------------------------------------------------------------------------
// CSR-by-dst build (vectorized; block-atomic slot allocation — no global scan)
// ---------------------------------------------------------------------------
__global__ void hist_kernel(const int* __restrict__ dst, int* __restrict__ cnt, int E)
{
    int i = blockIdx.x * blockDim.x + threadIdx.x;
    int base = i * 4;
    if (base + 3 < E) {
        int4 d = *(const int4*)(dst + base);
        atomicAdd(&cnt[d.x], 1);
        atomicAdd(&cnt[d.y], 1);
        atomicAdd(&cnt[d.z], 1);
        atomicAdd(&cnt[d.w], 1);
    } else {
        for (int j = base; j < E; j++) atomicAdd(&cnt[dst[j]], 1);
    }
}

#define SCAN_CHUNK 1024
__global__ void scan_alloc_kernel(const int* __restrict__ cnt,
                                  int* __restrict__ rowptr, int* __restrict__ cursor,
                                  int* __restrict__ counter, int N)
{
    __shared__ int s[SCAN_CHUNK];
    __shared__ int base;
    int i = blockIdx.x * SCAN_CHUNK + threadIdx.x;
    int v = (i < N) ? cnt[i] : 0;
    s[threadIdx.x] = v;
    __syncthreads();
#pragma unroll
    for (int off = 1; off < SCAN_CHUNK; off <<= 1) {
        int t = (threadIdx.x >= off) ? s[threadIdx.x - off] : 0;
        __syncthreads();
        s[threadIdx.x] += t;
        __syncthreads();
    }
    if (threadIdx.x == SCAN_CHUNK - 1)
        base = atomicAdd(counter, s[threadIdx.x]);
    __syncthreads();
    if (i < N) {
        int r = base + s[threadIdx.x] - v;
        rowptr[i] = r;
        cursor[i] = r;
    }
}

__global__ void fill_csr_kernel(const int* __restrict__ src, const int* __restrict__ dst,
                                int* __restrict__ cursor, int* __restrict__ eidx, int E)
{
    int i = blockIdx.x * blockDim.x + threadIdx.x;
    int base = i * 4;
    if (base + 3 < E) {
        int4 d = *(const int4*)(dst + base);
        int4 s = *(const int4*)(src + base);
        eidx[atomicAdd(&cursor[d.x], 1)] = s.x;
        eidx[atomicAdd(&cursor[d.y], 1)] = s.y;
        eidx[atomicAdd(&cursor[d.z], 1)] = s.z;
        eidx[atomicAdd(&cursor[d.w], 1)] = s.w;
    } else {
        for (int j = base; j < E; j++)
            eidx[atomicAdd(&cursor[dst[j]], 1)] = src[j];
    }
}

// ---------------------------------------------------------------------------
// Gather-max over fp16 rows: one warp per dst node, lane owns 4 halfs.
// ---------------------------------------------------------------------------
__global__ void gather_max_kernel(const uint2* __restrict__ p2,
                                  const int* __restrict__ rowptr,
                                  const int* __restrict__ cnt,
                                  const int* __restrict__ eidx,
                                  __half2* __restrict__ agg, int N)
{
    int warp = (blockIdx.x * blockDim.x + threadIdx.x) >> 5;
    int lane = threadIdx.x & 31;
    if (warp >= N) return;
    int beg = __ldg(&rowptr[warp]);
    int end = beg + __ldg(&cnt[warp]);

    __half2 z = __float2half2_rn(0.f);
    __half2 a0 = z, a1 = z;
    int i = beg;
    for (; i + 3 < end; i += 4) {
        int s0 = __ldg(&eidx[i]);
        int s1 = __ldg(&eidx[i + 1]);
        int s2 = __ldg(&eidx[i + 2]);
        int s3 = __ldg(&eidx[i + 3]);
        uint2 u0 = __ldg(p2 + (size_t)s0 * 32 + lane);
        uint2 u1 = __ldg(p2 + (size_t)s1 * 32 + lane);
        uint2 u2 = __ldg(p2 + (size_t)s2 * 32 + lane);
        uint2 u3 = __ldg(p2 + (size_t)s3 * 32 + lane);
        a0 = __hmax2(a0, __hmax2(__hmax2(*(__half2*)&u0.x, *(__half2*)&u1.x),
                                 __hmax2(*(__half2*)&u2.x, *(__half2*)&u3.x)));
        a1 = __hmax2(a1, __hmax2(__hmax2(*(__half2*)&u0.y, *(__half2*)&u1.y),
                                 __hmax2(*(__half2*)&u2.y, *(__half2*)&u3.y)));
    }
    for (; i < end; i++) {
        int s = __ldg(&eidx[i]);
        uint2 u = __ldg(p2 + (size_t)s * 32 + lane);
        a0 = __hmax2(a0, *(__half2*)&u.x);
        a1 = __hmax2(a1, *(__half2*)&u.y);
    }
    __half2 o[2] = {a0, a1};
    *(float2*)(agg + (size_t)warp * 64 + lane * 2) = *(float2*)o;
}

// ---------------------------------------------------------------------------
extern "C" void kernel_launch(void* const* d_in, const int* in_sizes, int n_in,
                              void* d_out, int out_size)
{
    const float* x       = (const float*)d_in[0];
    const int*   src     = (const int*)  d_in[1];
    const int*   dst     = (const int*)  d_in[2];
    const float* W_pool1 = (const float*)d_in[3];
    const float* b_pool1 = (const float*)d_in[4];
    const float* W_self1 = (const float*)d_in[5];
    const float* W_neigh1= (const float*)d_in[6];
    const float* b1      = (const float*)d_in[7];
    const float* W_pool2 = (const float*)d_in[8];
    const float* b_pool2 = (const float*)d_in[9];
    const float* W_self2 = (const float*)d_in[10];
    const float* W_neigh2= (const float*)d_in[11];
    const float* b2      = (const float*)d_in[12];

    const int M = in_sizes[0] / F;       // 50000
    const int E = in_sizes[1];           // 1600000

    __half *p, *agg, *h1, *x16, *w;
    int *cnt, *rowptr, *cursor, *eidx;
    cudaGetSymbolAddress((void**)&p,      g_p);
    cudaGetSymbolAddress((void**)&agg,    g_agg);
    cudaGetSymbolAddress((void**)&h1,     g_h1);
    cudaGetSymbolAddress((void**)&x16,    g_x16);
    cudaGetSymbolAddress((void**)&w,      g_w);
    cudaGetSymbolAddress((void**)&cnt,    g_cnt);
    cudaGetSymbolAddress((void**)&rowptr, g_rowptr);
    cudaGetSymbolAddress((void**)&cursor, g_cursor);
    cudaGetSymbolAddress((void**)&eidx,   g_eidx);
    float* out = (float*)d_out;
    int* counter = cnt + (NMAX - 1);

    const __half* rWp1 = w + 0 * F * F;
    const __half* rWs1 = w + 1 * F * F;
    const __half* rWn1 = w + 2 * F * F;
    const __half* rWp2 = w + 3 * F * F;
    const __half* rWs2 = w + 4 * F * F;
    const __half* rWn2 = w + 5 * F * F;

    auto k_fused1 = fused_gemm_kernel<true,  true >;
    auto k_fused2 = fused_gemm_kernel<false, false>;
    cudaFuncSetAttribute(pool1_kernel, cudaFuncAttributeMaxDynamicSharedMemorySize, SMEM_BYTES);
    cudaFuncSetAttribute(k_fused1, cudaFuncAttributeMaxDynamicSharedMemorySize, FUSED_SMEM);
    cudaFuncSetAttribute(k_fused2, cudaFuncAttributeMaxDynamicSharedMemorySize, FUSED_SMEM);

    const int gblocks = (M + 63) / 64;
    const int e4blocks = (E / 4 + 255) / 256;
    const int nb      = (M + SCAN_CHUNK - 1) / SCAN_CHUNK;
    const int wblocks = (M * 32 + 255) / 256;

    // --- side stream + events (host objects only; created once) ---
    static cudaStream_t s_csr = nullptr;
    static cudaEvent_t ev_fork = nullptr, ev_csr = nullptr;
    if (s_csr == nullptr) {
        cudaStreamCreateWithFlags(&s_csr, cudaStreamNonBlocking);
        cudaEventCreateWithFlags(&ev_fork, cudaEventDisableTiming);
        cudaEventCreateWithFlags(&ev_csr, cudaEventDisableTiming);
    }

    // Fork: CSR build overlaps conv_w + pool1.
    cudaEventRecord(ev_fork, 0);
    cudaStreamWaitEvent(s_csr, ev_fork, 0);
    cudaMemsetAsync(cnt, 0, (size_t)NMAX * sizeof(int), s_csr);
    hist_kernel<<<e4blocks, 256, 0, s_csr>>>(dst, cnt, E);

    conv_w_kernel<<<dim3(8, 6), 256>>>(W_pool1, W_self1, W_neigh1,
                                       W_pool2, W_self2, W_neigh2, w);
    scan_alloc_kernel<<<nb, SCAN_CHUNK, 0, s_csr>>>(cnt, rowptr, cursor, counter, M);
    pool1_kernel<<<gblocks, 256, SMEM_BYTES>>>(x, rWp1, b_pool1, x16, p, M);
    fill_csr_kernel<<<e4blocks, 256, 0, s_csr>>>(src, dst, cursor, eidx, E);
    cudaEventRecord(ev_csr, s_csr);

    // ---- Layer 1 (gather + fused h1 + pool2 -> p) ----
    cudaStreamWaitEvent(0, ev_csr, 0);
    gather_max_kernel<<<wblocks, 256>>>((const uint2*)p, rowptr, cnt, eidx, (__half2*)agg, M);
    k_fused1<<<gblocks, 256, FUSED_SMEM>>>(
        x16, rWs1, agg, rWn1, b1, h1, rWp2, b_pool2, p, M);

    // ---- Layer 2 ----
    gather_max_kernel<<<wblocks, 256>>>((const uint2*)p, rowptr, cnt, eidx, (__half2*)agg, M);
    k_fused2<<<gblocks, 256, FUSED_SMEM>>>(
        h1, rWs2, agg, rWn2, b2, out, nullptr, nullptr, nullptr, M);
}

// round 17
// speedup vs baseline: 1.0190x; 1.0190x over previous
#include <cuda_runtime.h>
#include <cuda_fp16.h>
#include <cstdint>

// Problem constants (from reference setup_inputs)
#define NMAX 50048
#define EMAX 1600000
#define F 128

// Scratch (allocation-free rule: __device__ globals)
__device__ __align__(16) __half g_p[NMAX * F];    // pool outputs (p1, then p2)
__device__ __align__(16) __half g_agg[NMAX * F];  // segment max
__device__ __align__(16) __half g_h1[NMAX * F];   // layer-1 output
__device__ __align__(16) __half g_x16[NMAX * F];  // fp16 copy of x (written by pool1)
__device__ __align__(16) __half g_w[6 * F * F];   // fp16 weights

// CSR-by-dst scratch (g_cnt[NMAX-1] doubles as the slot-allocator counter)
__device__ int g_cnt[NMAX];
__device__ int g_rowptr[NMAX + 1];
__device__ int g_cursor[NMAX];
__device__ int g_eidx[EMAX];

// ---------------------------------------------------------------------------
// Helpers
// ---------------------------------------------------------------------------
__device__ __forceinline__ void cp16(void* smem_dst, const void* gsrc) {
    unsigned d = (unsigned)__cvta_generic_to_shared(smem_dst);
    asm volatile("cp.async.cg.shared.global [%0], [%1], 16;" :: "r"(d), "l"(gsrc));
}
#define CP_COMMIT() asm volatile("cp.async.commit_group;")
#define CP_WAIT0()  asm volatile("cp.async.wait_group 0;")

template<int N>
__device__ __forceinline__ void cp_wait() {
    asm volatile("cp.async.wait_group %0;" :: "n"(N));
}

__device__ __forceinline__ void mma_f16(float* d, const unsigned* a, const unsigned* b) {
    asm volatile(
        "mma.sync.aligned.m16n8k16.row.col.f32.f16.f16.f32 "
        "{%0,%1,%2,%3}, {%4,%5,%6,%7}, {%8,%9}, {%0,%1,%2,%3};"
        : "+f"(d[0]), "+f"(d[1]), "+f"(d[2]), "+f"(d[3])
        : "r"(a[0]), "r"(a[1]), "r"(a[2]), "r"(a[3]), "r"(b[0]), "r"(b[1]));
}

__device__ __forceinline__ void ldsm_x4(unsigned* a, unsigned saddr) {
    asm volatile("ldmatrix.sync.aligned.m8n8.x4.shared.b16 {%0,%1,%2,%3}, [%4];"
        : "=r"(a[0]), "=r"(a[1]), "=r"(a[2]), "=r"(a[3]) : "r"(saddr));
}
__device__ __forceinline__ void ldsm_x2_trans(unsigned* b, unsigned saddr) {
    asm volatile("ldmatrix.sync.aligned.m8n8.x2.trans.shared.b16 {%0,%1}, [%2];"
        : "=r"(b[0]), "=r"(b[1]) : "r"(saddr));
}
// x4 trans: loads a 16(k) x 16(n) b16 tile = fragments for TWO adjacent n-frags.
__device__ __forceinline__ void ldsm_x4_trans(unsigned* b, unsigned saddr) {
    asm volatile("ldmatrix.sync.aligned.m8n8.x4.trans.shared.b16 {%0,%1,%2,%3}, [%4];"
        : "=r"(b[0]), "=r"(b[1]), "=r"(b[2]), "=r"(b[3]) : "r"(saddr));
}

// ---------------------------------------------------------------------------
// Prep: convert 6 weight matrices to fp16 (once per launch)
// ---------------------------------------------------------------------------
__global__ void conv_w_kernel(const float* w0, const float* w1, const float* w2,
                              const float* w3, const float* w4, const float* w5,
                              __half* __restrict__ out)
{
    const float* ws[6] = {w0, w1, w2, w3, w4, w5};
    const float* in = ws[blockIdx.y];
    __half* o = out + blockIdx.y * (F * F);
    int i = blockIdx.x * blockDim.x + threadIdx.x;
    float4 v0 = ((const float4*)in)[i * 2];
    float4 v1 = ((const float4*)in)[i * 2 + 1];
    __half2 h[4];
    h[0] = __floats2half2_rn(v0.x, v0.y);
    h[1] = __floats2half2_rn(v0.z, v0.w);
    h[2] = __floats2half2_rn(v1.x, v1.y);
    h[3] = __floats2half2_rn(v1.z, v1.w);
    ((float4*)o)[i] = *(float4*)h;
}

// ---------------------------------------------------------------------------
// Tiling constants
// ---------------------------------------------------------------------------
#define SAH 72
#define SBH 136
#define AS_ELEM (64 * SAH)
#define BS_ELEM (64 * SBH)
#define AS_BYTES (AS_ELEM * 2)
#define BS_BYTES (BS_ELEM * 2)
#define SMEM_BYTES (2 * AS_BYTES + 2 * BS_BYTES)      // pool1 (2-buffer)
#define H1_STRIDE 136
#define ROWSQ_OFF 17408
// Fused kernel: 4 A buffers + 4 B buffers, full prefetch
#define FB_OFF (4 * AS_BYTES)
#define FUSED_SMEM (4 * AS_BYTES + 4 * BS_BYTES)      // 106496 bytes

__device__ __forceinline__ void prefetch_A(char* smc, const __half* A,
                                           int buf, int kk, int m0, int M, int tid)
{
    __half* As = (__half*)smc;
#pragma unroll
    for (int i = 0; i < 2; i++) {
        int c  = tid + i * 256;
        int r  = c >> 3;
        int c8 = (c & 7) * 8;
        int m  = m0 + r;
        if (m < M)
            cp16(&As[buf * AS_ELEM + r * SAH + c8], A + (size_t)m * F + kk + c8);
    }
}

__device__ __forceinline__ void prefetch_B2(char* smc, const __half* W,
                                            int buf, int kk, int tid)
{
    __half* Bs = (__half*)(smc + 2 * AS_BYTES);   // pool1 layout (2 A bufs)
#pragma unroll
    for (int i = 0; i < 4; i++) {
        int c  = tid + i * 256;
        int r  = c >> 4;
        int n8 = (c & 15) * 8;
        cp16(&Bs[buf * BS_ELEM + r * SBH + n8], W + (size_t)(kk + r) * F + n8);
    }
}

__device__ __forceinline__ void prefetch_B4(char* smc, const __half* W,
                                            int buf, int kk, int tid)
{
    __half* Bs = (__half*)(smc + FB_OFF);         // fused layout (4 A bufs)
#pragma unroll
    for (int i = 0; i < 4; i++) {
        int c  = tid + i * 256;
        int r  = c >> 4;
        int n8 = (c & 15) * 8;
        cp16(&Bs[buf * BS_ELEM + r * SBH + n8], W + (size_t)(kk + r) * F + n8);
    }
}

// ---------------------------------------------------------------------------
// Pool GEMM layer 1, fused x-conversion.
// ---------------------------------------------------------------------------
__global__ __launch_bounds__(256, 3)
void pool1_kernel(const float* __restrict__ x, const __half* __restrict__ W1,
                  const float* __restrict__ bias,
                  __half* __restrict__ x16, __half* __restrict__ Pout, int M)
{
    extern __shared__ __align__(16) char smc[];
    __half* As = (__half*)smc;

    const int tid  = threadIdx.x;
    const int wid  = tid >> 5;
    const int lane = tid & 31;
    const int wr   = wid >> 2;
    const int wc   = wid & 3;
    const int g    = lane >> 2;
    const int tig  = lane & 3;
    const int m0   = blockIdx.x * 64;

    prefetch_B2(smc, W1, 0, 0, tid);
    prefetch_B2(smc, W1, 1, 64, tid);
    CP_COMMIT();

#pragma unroll
    for (int t = 0; t < 2; t++) {
        float4 v[4];
        int rr[4], cc[4];
#pragma unroll
        for (int i = 0; i < 4; i++) {
            int idx = tid + i * 256;
            rr[i] = idx >> 4;
            cc[i] = (idx & 15) * 4;
            int m = m0 + rr[i];
            v[i] = make_float4(0.f, 0.f, 0.f, 0.f);
            if (m < M) v[i] = *(const float4*)(x + (size_t)m * F + t * 64 + cc[i]);
        }
#pragma unroll
        for (int i = 0; i < 4; i++) {
            __half2 h0 = __floats2half2_rn(v[i].x, v[i].y);
            __half2 h1 = __floats2half2_rn(v[i].z, v[i].w);
            __half2 pair[2] = {h0, h1};
            *(uint2*)(As + t * AS_ELEM + rr[i] * SAH + cc[i]) = *(uint2*)pair;
            int m = m0 + rr[i];
            if (m < M)
                *(uint2*)(x16 + (size_t)m * F + t * 64 + cc[i]) = *(uint2*)pair;
        }
    }

    unsigned as_u32 = (unsigned)__cvta_generic_to_shared(smc);
    unsigned bs_u32 = (unsigned)__cvta_generic_to_shared(smc + 2 * AS_BYTES);
    const int lrow = lane & 15;
    const int kadd = (lane & 16) ? 8 : 0;
    unsigned aaddr[2];
#pragma unroll
    for (int mf = 0; mf < 2; mf++)
        aaddr[mf] = as_u32 + ((wr * 32 + mf * 16 + lrow) * SAH + kadd) * 2;
    unsigned baddr2[2];
#pragma unroll
    for (int j = 0; j < 2; j++)
        baddr2[j] = bs_u32 + (lrow * SBH + wc * 32 + j * 16 + kadd) * 2;

    float acc[2][4][4];
#pragma unroll
    for (int mf = 0; mf < 2; mf++)
#pragma unroll
        for (int nf = 0; nf < 4; nf++)
#pragma unroll
            for (int q = 0; q < 4; q++) acc[mf][nf][q] = 0.0f;

    CP_WAIT0();
    __syncthreads();

#pragma unroll
    for (int t = 0; t < 2; t++) {
#pragma unroll
        for (int s = 0; s < 4; s++) {
            unsigned a[2][4], b[2][4];
#pragma unroll
            for (int mf = 0; mf < 2; mf++)
                ldsm_x4(a[mf], aaddr[mf] + t * AS_BYTES + s * 32);
#pragma unroll
            for (int j = 0; j < 2; j++)
                ldsm_x4_trans(b[j], baddr2[j] + t * BS_BYTES + s * (16 * SBH * 2));
#pragma unroll
            for (int mf = 0; mf < 2; mf++)
#pragma unroll
                for (int nf = 0; nf < 4; nf++)
                    mma_f16(acc[mf][nf], a[mf], &b[nf >> 1][(nf & 1) * 2]);
        }
    }

    float bv0[4], bv1[4];
#pragma unroll
    for (int nf = 0; nf < 4; nf++) {
        int cb = wc * 32 + nf * 8 + 2 * tig;
        bv0[nf] = bias[cb];
        bv1[nf] = bias[cb + 1];
    }
#pragma unroll
    for (int mf = 0; mf < 2; mf++) {
#pragma unroll
        for (int half = 0; half < 2; half++) {
            int m = m0 + wr * 32 + mf * 16 + half * 8 + g;
            if (m >= M) continue;
#pragma unroll
            for (int nf = 0; nf < 4; nf++) {
                float v0 = fmaxf(acc[mf][nf][half * 2 + 0] + bv0[nf], 0.f);
                float v1 = fmaxf(acc[mf][nf][half * 2 + 1] + bv1[nf], 0.f);
                int col = wc * 32 + nf * 8 + 2 * tig;
                __half2 hv = __floats2half2_rn(v0, v1);
                *(__half2*)(Pout + (size_t)m * F + col) = hv;
            }
        }
    }
}

// ---------------------------------------------------------------------------
// Fused GEMM (R15 variant, best-measured): 4 A + 4 B buffers, all loads issued
// at entry in 4 groups; per-tile decreasing wait depth; x2-trans B loads.
// C = epi( A1@W1 + A2@W2 + bias ); optional POOL2 tail from smem C tile.
// ---------------------------------------------------------------------------
template<bool HALFOUT, bool POOL2>
__global__ __launch_bounds__(256, 2)
void fused_gemm_kernel(const __half* __restrict__ A1, const __half* __restrict__ W1,
                       const __half* __restrict__ A2, const __half* __restrict__ W2,
                       const float* __restrict__ bias, void* __restrict__ Cout,
                       const __half* __restrict__ Wp2, const float* __restrict__ bias2,
                       __half* __restrict__ Pout, int M)
{
    extern __shared__ __align__(16) char smc[];

    const int tid  = threadIdx.x;
    const int wid  = tid >> 5;
    const int lane = tid & 31;
    const int wr   = wid >> 2;
    const int wc   = wid & 3;
    const int g    = lane >> 2;
    const int tig  = lane & 3;
    const int m0   = blockIdx.x * 64;

    // Issue all 4 tile loads up front (groups 0..3).
    prefetch_A(smc, A1, 0, 0,  m0, M, tid); prefetch_B4(smc, W1, 0, 0,  tid); CP_COMMIT();
    prefetch_A(smc, A1, 1, 64, m0, M, tid); prefetch_B4(smc, W1, 1, 64, tid); CP_COMMIT();
    prefetch_A(smc, A2, 2, 0,  m0, M, tid); prefetch_B4(smc, W2, 2, 0,  tid); CP_COMMIT();
    prefetch_A(smc, A2, 3, 64, m0, M, tid); prefetch_B4(smc, W2, 3, 64, tid); CP_COMMIT();

    unsigned as_u32 = (unsigned)__cvta_generic_to_shared(smc);
    unsigned bs_u32 = (unsigned)__cvta_generic_to_shared(smc + FB_OFF);
    const int lrow = lane & 15;
    const int kadd = (lane & 16) ? 8 : 0;
    unsigned aaddr[2];
#pragma unroll
    for (int mf = 0; mf < 2; mf++)
        aaddr[mf] = as_u32 + ((wr * 32 + mf * 16 + lrow) * SAH + kadd) * 2;
    unsigned baddr[4];
#pragma unroll
    for (int nf = 0; nf < 4; nf++)
        baddr[nf] = bs_u32 + (lrow * SBH + (wc * 32 + nf * 8)) * 2;

    float acc[2][4][4];
#pragma unroll
    for (int mf = 0; mf < 2; mf++)
#pragma unroll
        for (int nf = 0; nf < 4; nf++)
#pragma unroll
            for (int q = 0; q < 4; q++) acc[mf][nf][q] = 0.0f;

#pragma unroll
    for (int t = 0; t < 4; t++) {
        if (t == 0)      cp_wait<3>();
        else if (t == 1) cp_wait<2>();
        else if (t == 2) cp_wait<1>();
        else             cp_wait<0>();
        __syncthreads();

#pragma unroll
        for (int s = 0; s < 4; s++) {
            unsigned a[2][4], b[4][2];
#pragma unroll
            for (int mf = 0; mf < 2; mf++)
                ldsm_x4(a[mf], aaddr[mf] + t * AS_BYTES + s * 32);
#pragma unroll
            for (int nf = 0; nf < 4; nf++)
                ldsm_x2_trans(b[nf], baddr[nf] + t * BS_BYTES + s * (16 * SBH * 2));
#pragma unroll
            for (int mf = 0; mf < 2; mf++)
#pragma unroll
                for (int nf = 0; nf < 4; nf++)
                    mma_f16(acc[mf][nf], a[mf], b[nf]);
        }
    }

    // ---- epilogue ----
    __syncthreads();

    if (POOL2) {
        // prefetch full Wp2 into B buffers 0,1 (dead now)
#pragma unroll
        for (int i = 0; i < 8; i++) {
            int c   = tid + i * 256;
            int buf = c >> 10;
            int cc  = c & 1023;
            int r   = cc >> 4;
            int n8  = (cc & 15) * 8;
            cp16((__half*)(smc + FB_OFF) + buf * BS_ELEM + r * SBH + n8,
                 Wp2 + (size_t)(buf * 64 + r) * F + n8);
        }
        CP_COMMIT();
    }

    float bv0[4], bv1[4];
#pragma unroll
    for (int nf = 0; nf < 4; nf++) {
        int cb = wc * 32 + nf * 8 + 2 * tig;
        bv0[nf] = bias[cb];
        bv1[nf] = bias[cb + 1];
    }
#pragma unroll
    for (int mf = 0; mf < 2; mf++)
#pragma unroll
        for (int nf = 0; nf < 4; nf++) {
            acc[mf][nf][0] += bv0[nf];
            acc[mf][nf][1] += bv1[nf];
            acc[mf][nf][2] += bv0[nf];
            acc[mf][nf][3] += bv1[nf];
        }

    // L2 norm (always on for fused layers)
    float inv[2][2];
    {
        float* rowsq = (float*)(smc + ROWSQ_OFF);
        if (tid < 64) rowsq[tid] = 0.0f;
        __syncthreads();
#pragma unroll
        for (int mf = 0; mf < 2; mf++) {
#pragma unroll
            for (int half = 0; half < 2; half++) {
                float s = 0.f;
#pragma unroll
                for (int nf = 0; nf < 4; nf++) {
                    float v0 = acc[mf][nf][half * 2 + 0];
                    float v1 = acc[mf][nf][half * 2 + 1];
                    s = fmaf(v0, v0, fmaf(v1, v1, s));
                }
                s += __shfl_xor_sync(0xffffffffu, s, 1);
                s += __shfl_xor_sync(0xffffffffu, s, 2);
                if (tig == 0) {
                    int r = wr * 32 + mf * 16 + half * 8 + g;
                    atomicAdd(&rowsq[r], s);
                }
            }
        }
        __syncthreads();
#pragma unroll
        for (int mf = 0; mf < 2; mf++)
#pragma unroll
            for (int half = 0; half < 2; half++) {
                int r = wr * 32 + mf * 16 + half * 8 + g;
                inv[mf][half] = 1.0f / fmaxf(sqrtf(rowsq[r]), 1e-12f);
            }
    }

    // store (relu); POOL2 mirrors the C tile into smem (A region, dead)
#pragma unroll
    for (int mf = 0; mf < 2; mf++) {
#pragma unroll
        for (int half = 0; half < 2; half++) {
            int mloc = wr * 32 + mf * 16 + half * 8 + g;
            int m = m0 + mloc;
            float s = inv[mf][half];
#pragma unroll
            for (int nf = 0; nf < 4; nf++) {
                float v0 = fmaxf(acc[mf][nf][half * 2 + 0] * s, 0.f);
                float v1 = fmaxf(acc[mf][nf][half * 2 + 1] * s, 0.f);
                int col = wc * 32 + nf * 8 + 2 * tig;
                if (HALFOUT) {
                    __half2 hv = __floats2half2_rn(v0, v1);
                    if (m < M)
                        *(__half2*)((__half*)Cout + (size_t)m * F + col) = hv;
                    if (POOL2)
                        *(__half2*)(smc + (mloc * H1_STRIDE + col) * 2) = hv;
                } else {
                    if (m < M)
                        *(float2*)((float*)Cout + (size_t)m * F + col) = make_float2(v0, v1);
                }
            }
        }
    }

    if (POOL2) {
        CP_WAIT0();
        __syncthreads();

        unsigned a2addr[2];
#pragma unroll
        for (int mf = 0; mf < 2; mf++)
            a2addr[mf] = as_u32 + ((wr * 32 + mf * 16 + lrow) * H1_STRIDE + kadd) * 2;

        float acc2[2][4][4];
#pragma unroll
        for (int mf = 0; mf < 2; mf++)
#pragma unroll
            for (int nf = 0; nf < 4; nf++)
#pragma unroll
                for (int q = 0; q < 4; q++) acc2[mf][nf][q] = 0.0f;

#pragma unroll
        for (int t = 0; t < 2; t++) {
#pragma unroll
            for (int s = 0; s < 4; s++) {
                unsigned a[2][4], b[4][2];
#pragma unroll
                for (int mf = 0; mf < 2; mf++)
                    ldsm_x4(a[mf], a2addr[mf] + (t * 64 + s * 16) * 2);
#pragma unroll
                for (int nf = 0; nf < 4; nf++)
                    ldsm_x2_trans(b[nf], baddr[nf] + t * BS_BYTES + s * (16 * SBH * 2));
#pragma unroll
                for (int mf = 0; mf < 2; mf++)
#pragma unroll
                    for (int nf = 0; nf < 4; nf++)
                        mma_f16(acc2[mf][nf], a[mf], b[nf]);
            }
        }

        float pb0[4], pb1[4];
#pragma unroll
        for (int nf = 0; nf < 4; nf++) {
            int cb = wc * 32 + nf * 8 + 2 * tig;
            pb0[nf] = bias2[cb];
            pb1[nf] = bias2[cb + 1];
        }
#pragma unroll
        for (int mf = 0; mf < 2; mf++) {
#pragma unroll
            for (int half = 0; half < 2; half++) {
                int m = m0 + wr * 32 + mf * 16 + half * 8 + g;
                if (m >= M) continue;
#pragma unroll
                for (int nf = 0; nf < 4; nf++) {
                    float v0 = fmaxf(acc2[mf][nf][half * 2 + 0] + pb0[nf], 0.f);
                    float v1 = fmaxf(acc2[mf][nf][half * 2 + 1] + pb1[nf], 0.f);
                    int col = wc * 32 + nf * 8 + 2 * tig;
                    __half2 hv = __floats2half2_rn(v0, v1);
                    *(__half2*)(Pout + (size_t)m * F + col) = hv;
                }
            }
        }
    }
}

// ---------------------------------------------------------------------------
// CSR-by-dst build (vectorized; block-atomic slot allocation — no global scan)
// ---------------------------------------------------------------------------
__global__ void hist_kernel(const int* __restrict__ dst, int* __restrict__ cnt, int E)
{
    int i = blockIdx.x * blockDim.x + threadIdx.x;
    int base = i * 4;
    if (base + 3 < E) {
        int4 d = *(const int4*)(dst + base);
        atomicAdd(&cnt[d.x], 1);
        atomicAdd(&cnt[d.y], 1);
        atomicAdd(&cnt[d.z], 1);
        atomicAdd(&cnt[d.w], 1);
    } else {
        for (int j = base; j < E; j++) atomicAdd(&cnt[dst[j]], 1);
    }
}

#define SCAN_CHUNK 1024
__global__ void scan_alloc_kernel(const int* __restrict__ cnt,
                                  int* __restrict__ rowptr, int* __restrict__ cursor,
                                  int* __restrict__ counter, int N)
{
    __shared__ int s[SCAN_CHUNK];
    __shared__ int base;
    int i = blockIdx.x * SCAN_CHUNK + threadIdx.x;
    int v = (i < N) ? cnt[i] : 0;
    s[threadIdx.x] = v;
    __syncthreads();
#pragma unroll
    for (int off = 1; off < SCAN_CHUNK; off <<= 1) {
        int t = (threadIdx.x >= off) ? s[threadIdx.x - off] : 0;
        __syncthreads();
        s[threadIdx.x] += t;
        __syncthreads();
    }
    if (threadIdx.x == SCAN_CHUNK - 1)
        base = atomicAdd(counter, s[threadIdx.x]);
    __syncthreads();
    if (i < N) {
        int r = base + s[threadIdx.x] - v;
        rowptr[i] = r;
        cursor[i] = r;
    }
}

__global__ void fill_csr_kernel(const int* __restrict__ src, const int* __restrict__ dst,
                                int* __restrict__ cursor, int* __restrict__ eidx, int E)
{
    int i = blockIdx.x * blockDim.x + threadIdx.x;
    int base = i * 4;
    if (base + 3 < E) {
        int4 d = *(const int4*)(dst + base);
        int4 s = *(const int4*)(src + base);
        eidx[atomicAdd(&cursor[d.x], 1)] = s.x;
        eidx[atomicAdd(&cursor[d.y], 1)] = s.y;
        eidx[atomicAdd(&cursor[d.z], 1)] = s.z;
        eidx[atomicAdd(&cursor[d.w], 1)] = s.w;
    } else {
        for (int j = base; j < E; j++)
            eidx[atomicAdd(&cursor[dst[j]], 1)] = src[j];
    }
}

// ---------------------------------------------------------------------------
// Gather-max over fp16 rows: one warp per dst node, lane owns 4 halfs.
// ---------------------------------------------------------------------------
__global__ void gather_max_kernel(const uint2* __restrict__ p2,
                                  const int* __restrict__ rowptr,
                                  const int* __restrict__ cnt,
                                  const int* __restrict__ eidx,
                                  __half2* __restrict__ agg, int N)
{
    int warp = (blockIdx.x * blockDim.x + threadIdx.x) >> 5;
    int lane = threadIdx.x & 31;
    if (warp >= N) return;
    int beg = __ldg(&rowptr[warp]);
    int end = beg + __ldg(&cnt[warp]);

    __half2 z = __float2half2_rn(0.f);
    __half2 a0 = z, a1 = z;
    int i = beg;
    for (; i + 3 < end; i += 4) {
        int s0 = __ldg(&eidx[i]);
        int s1 = __ldg(&eidx[i + 1]);
        int s2 = __ldg(&eidx[i + 2]);
        int s3 = __ldg(&eidx[i + 3]);
        uint2 u0 = __ldg(p2 + (size_t)s0 * 32 + lane);
        uint2 u1 = __ldg(p2 + (size_t)s1 * 32 + lane);
        uint2 u2 = __ldg(p2 + (size_t)s2 * 32 + lane);
        uint2 u3 = __ldg(p2 + (size_t)s3 * 32 + lane);
        a0 = __hmax2(a0, __hmax2(__hmax2(*(__half2*)&u0.x, *(__half2*)&u1.x),
                                 __hmax2(*(__half2*)&u2.x, *(__half2*)&u3.x)));
        a1 = __hmax2(a1, __hmax2(__hmax2(*(__half2*)&u0.y, *(__half2*)&u1.y),
                                 __hmax2(*(__half2*)&u2.y, *(__half2*)&u3.y)));
    }
    for (; i < end; i++) {
        int s = __ldg(&eidx[i]);
        uint2 u = __ldg(p2 + (size_t)s * 32 + lane);
        a0 = __hmax2(a0, *(__half2*)&u.x);
        a1 = __hmax2(a1, *(__half2*)&u.y);
    }
    __half2 o[2] = {a0, a1};
    *(float2*)(agg + (size_t)warp * 64 + lane * 2) = *(float2*)o;
}

// ---------------------------------------------------------------------------
extern "C" void kernel_launch(void* const* d_in, const int* in_sizes, int n_in,
                              void* d_out, int out_size)
{
    const float* x       = (const float*)d_in[0];
    const int*   src     = (const int*)  d_in[1];
    const int*   dst     = (const int*)  d_in[2];
    const float* W_pool1 = (const float*)d_in[3];
    const float* b_pool1 = (const float*)d_in[4];
    const float* W_self1 = (const float*)d_in[5];
    const float* W_neigh1= (const float*)d_in[6];
    const float* b1      = (const float*)d_in[7];
    const float* W_pool2 = (const float*)d_in[8];
    const float* b_pool2 = (const float*)d_in[9];
    const float* W_self2 = (const float*)d_in[10];
    const float* W_neigh2= (const float*)d_in[11];
    const float* b2      = (const float*)d_in[12];

    const int M = in_sizes[0] / F;       // 50000
    const int E = in_sizes[1];           // 1600000

    __half *p, *agg, *h1, *x16, *w;
    int *cnt, *rowptr, *cursor, *eidx;
    cudaGetSymbolAddress((void**)&p,      g_p);
    cudaGetSymbolAddress((void**)&agg,    g_agg);
    cudaGetSymbolAddress((void**)&h1,     g_h1);
    cudaGetSymbolAddress((void**)&x16,    g_x16);
    cudaGetSymbolAddress((void**)&w,      g_w);
    cudaGetSymbolAddress((void**)&cnt,    g_cnt);
    cudaGetSymbolAddress((void**)&rowptr, g_rowptr);
    cudaGetSymbolAddress((void**)&cursor, g_cursor);
    cudaGetSymbolAddress((void**)&eidx,   g_eidx);
    float* out = (float*)d_out;
    int* counter = cnt + (NMAX - 1);

    const __half* rWp1 = w + 0 * F * F;
    const __half* rWs1 = w + 1 * F * F;
    const __half* rWn1 = w + 2 * F * F;
    const __half* rWp2 = w + 3 * F * F;
    const __half* rWs2 = w + 4 * F * F;
    const __half* rWn2 = w + 5 * F * F;

    auto k_fused1 = fused_gemm_kernel<true,  true >;
    auto k_fused2 = fused_gemm_kernel<false, false>;
    cudaFuncSetAttribute(pool1_kernel, cudaFuncAttributeMaxDynamicSharedMemorySize, SMEM_BYTES);
    cudaFuncSetAttribute(k_fused1, cudaFuncAttributeMaxDynamicSharedMemorySize, FUSED_SMEM);
    cudaFuncSetAttribute(k_fused2, cudaFuncAttributeMaxDynamicSharedMemorySize, FUSED_SMEM);

    const int gblocks = (M + 63) / 64;
    const int e4blocks = (E / 4 + 255) / 256;
    const int nb      = (M + SCAN_CHUNK - 1) / SCAN_CHUNK;
    const int wblocks = (M * 32 + 255) / 256;

    // --- side stream + events (host objects only; created once) ---
    static cudaStream_t s_csr = nullptr;
    static cudaEvent_t ev_fork = nullptr, ev_csr = nullptr;
    if (s_csr == nullptr) {
        cudaStreamCreateWithFlags(&s_csr, cudaStreamNonBlocking);
        cudaEventCreateWithFlags(&ev_fork, cudaEventDisableTiming);
        cudaEventCreateWithFlags(&ev_csr, cudaEventDisableTiming);
    }

    // Fork: CSR build overlaps conv_w + pool1.
    cudaEventRecord(ev_fork, 0);
    cudaStreamWaitEvent(s_csr, ev_fork, 0);
    cudaMemsetAsync(cnt, 0, (size_t)NMAX * sizeof(int), s_csr);
    hist_kernel<<<e4blocks, 256, 0, s_csr>>>(dst, cnt, E);

    conv_w_kernel<<<dim3(8, 6), 256>>>(W_pool1, W_self1, W_neigh1,
                                       W_pool2, W_self2, W_neigh2, w);
    scan_alloc_kernel<<<nb, SCAN_CHUNK, 0, s_csr>>>(cnt, rowptr, cursor, counter, M);
    pool1_kernel<<<gblocks, 256, SMEM_BYTES>>>(x, rWp1, b_pool1, x16, p, M);
    fill_csr_kernel<<<e4blocks, 256, 0, s_csr>>>(src, dst, cursor, eidx, E);
    cudaEventRecord(ev_csr, s_csr);

    // ---- Layer 1 (gather + fused h1 + pool2 -> p) ----
    cudaStreamWaitEvent(0, ev_csr, 0);
    gather_max_kernel<<<wblocks, 256>>>((const uint2*)p, rowptr, cnt, eidx, (__half2*)agg, M);
    k_fused1<<<gblocks, 256, FUSED_SMEM>>>(
        x16, rWs1, agg, rWn1, b1, h1, rWp2, b_pool2, p, M);

    // ---- Layer 2 ----
    gather_max_kernel<<<wblocks, 256>>>((const uint2*)p, rowptr, cnt, eidx, (__half2*)agg, M);
    k_fused2<<<gblocks, 256, FUSED_SMEM>>>(
        h1, rWs2, agg, rWn2, b2, out, nullptr, nullptr, nullptr, M);
}